// round 8
// baseline (speedup 1.0000x reference)
#include <cuda_runtime.h>
#include <cuda_bf16.h>
#include <cstdint>
#include <cstddef>

#define S_LEN 4096
#define B_SZ  8
#define D_SZ  1024
#define M_TOT (B_SZ * S_LEN)

__device__ float g_gate[(size_t)M_TOT * D_SZ];
__device__ float g_proj[(size_t)M_TOT * D_SZ];
__device__ float g_state[2][B_SZ * D_SZ];
__device__ unsigned g_cnt[4];

typedef unsigned long long u64;

__device__ __forceinline__ u64 ffma2(u64 a, u64 b, u64 c) {
    u64 d;
    asm("fma.rn.f32x2 %0, %1, %2, %3;" : "=l"(d) : "l"(a), "l"(b), "l"(c));
    return d;
}
__device__ __forceinline__ float2 u2f(u64 v) {
    float2 f;
    asm("mov.b64 {%0, %1}, %2;" : "=f"(f.x), "=f"(f.y) : "l"(v));
    return f;
}
__device__ __forceinline__ void mma16816(float* c, const unsigned* a,
                                         unsigned b0, unsigned b1) {
    asm("mma.sync.aligned.m16n8k16.row.col.f32.bf16.bf16.f32 "
        "{%0,%1,%2,%3}, {%4,%5,%6,%7}, {%8,%9}, {%0,%1,%2,%3};"
        : "+f"(c[0]), "+f"(c[1]), "+f"(c[2]), "+f"(c[3])
        : "r"(a[0]), "r"(a[1]), "r"(a[2]), "r"(a[3]), "r"(b0), "r"(b1));
}
__device__ __forceinline__ void cvt_hilo(float x, float y,
                                         unsigned& h, unsigned& l) {
    __nv_bfloat16 hx = __float2bfloat16_rn(x);
    __nv_bfloat16 hy = __float2bfloat16_rn(y);
    __nv_bfloat16 lx = __float2bfloat16_rn(x - __bfloat162float(hx));
    __nv_bfloat16 ly = __float2bfloat16_rn(y - __bfloat162float(hy));
    h = (unsigned)__bfloat16_as_ushort(hx) | ((unsigned)__bfloat16_as_ushort(hy) << 16);
    l = (unsigned)__bfloat16_as_ushort(lx) | ((unsigned)__bfloat16_as_ushort(ly) << 16);
}

#define STRIDE 17

// ---------------------------------------------------------------------------
// Phase 1: z = X@Win^T + bin via mma.sync bf16 hi/lo (3 terms). (validated R7)
// CTA(0,0) also zeroes recurrence state + counters.
// ---------------------------------------------------------------------------
__global__ __launch_bounds__(256, 2) void phase1_hmma(
    const float* __restrict__ X, const float* __restrict__ Win,
    const float* __restrict__ bin)
{
    __shared__ unsigned Ah[128 * STRIDE], Al[128 * STRIDE];
    __shared__ unsigned Bh[128 * STRIDE], Bl[128 * STRIDE];

    const int tid = threadIdx.x;
    const int m0 = blockIdx.y * 128, n0 = blockIdx.x * 128;

    if (blockIdx.x == 0 && blockIdx.y == 0) {
        if (tid < 4) g_cnt[tid] = 0u;
        for (int i = tid; i < B_SZ * D_SZ; i += 256) g_state[0][i] = 0.0f;
    }

    const int lane = tid & 31, w = tid >> 5;
    const int m_off = (w & 3) * 32;
    const int n_off = (w >> 2) * 64;

    const int srow = tid >> 1;
    const int skh  = (tid & 1) * 16;
    const float* Ap = X   + (size_t)(m0 + srow) * D_SZ + skh;
    const float* Bp = Win + (size_t)(n0 + srow) * D_SZ + skh;
    const int sb32 = srow * STRIDE + (skh >> 1);

    float C[2][8][4];
    #pragma unroll
    for (int mt = 0; mt < 2; ++mt)
        #pragma unroll
        for (int nt = 0; nt < 8; ++nt)
            #pragma unroll
            for (int q = 0; q < 4; ++q) C[mt][nt][q] = 0.0f;

    const int fr = lane >> 2;
    const int fc = lane & 3;

    for (int k0 = 0; k0 < D_SZ; k0 += 32) {
        #pragma unroll
        for (int j = 0; j < 4; ++j) {
            float4 a = *(const float4*)(Ap + k0 + 4 * j);
            unsigned h0, l0, h1, l1;
            cvt_hilo(a.x, a.y, h0, l0);
            cvt_hilo(a.z, a.w, h1, l1);
            Ah[sb32 + 2 * j] = h0; Ah[sb32 + 2 * j + 1] = h1;
            Al[sb32 + 2 * j] = l0; Al[sb32 + 2 * j + 1] = l1;
            float4 b = *(const float4*)(Bp + k0 + 4 * j);
            cvt_hilo(b.x, b.y, h0, l0);
            cvt_hilo(b.z, b.w, h1, l1);
            Bh[sb32 + 2 * j] = h0; Bh[sb32 + 2 * j + 1] = h1;
            Bl[sb32 + 2 * j] = l0; Bl[sb32 + 2 * j + 1] = l1;
        }
        __syncthreads();

        #pragma unroll
        for (int ks = 0; ks < 2; ++ks) {
            const int cb = ks * 8 + fc;
            unsigned ah[2][4], al[2][4];
            #pragma unroll
            for (int mt = 0; mt < 2; ++mt) {
                int r = m_off + mt * 16 + fr;
                ah[mt][0] = Ah[r * STRIDE + cb];
                ah[mt][1] = Ah[(r + 8) * STRIDE + cb];
                ah[mt][2] = Ah[r * STRIDE + cb + 4];
                ah[mt][3] = Ah[(r + 8) * STRIDE + cb + 4];
                al[mt][0] = Al[r * STRIDE + cb];
                al[mt][1] = Al[(r + 8) * STRIDE + cb];
                al[mt][2] = Al[r * STRIDE + cb + 4];
                al[mt][3] = Al[(r + 8) * STRIDE + cb + 4];
            }
            #pragma unroll
            for (int nt = 0; nt < 8; ++nt) {
                int n = n_off + nt * 8 + fr;
                unsigned bh0 = Bh[n * STRIDE + cb], bh1 = Bh[n * STRIDE + cb + 4];
                unsigned bl0 = Bl[n * STRIDE + cb], bl1 = Bl[n * STRIDE + cb + 4];
                #pragma unroll
                for (int mt = 0; mt < 2; ++mt) {
                    mma16816(C[mt][nt], ah[mt], bh0, bh1);
                    mma16816(C[mt][nt], ah[mt], bl0, bl1);
                    mma16816(C[mt][nt], al[mt], bh0, bh1);
                }
            }
        }
        __syncthreads();
    }

    const bool is_gate = (n0 < D_SZ);
    float* dst = is_gate ? g_gate : g_proj;
    const int csub = is_gate ? 0 : D_SZ;
    #pragma unroll
    for (int mt = 0; mt < 2; ++mt) {
        const int r = m0 + m_off + mt * 16 + fr;
        #pragma unroll
        for (int nt = 0; nt < 8; ++nt) {
            const int cn = n0 + n_off + nt * 8 + fc * 2;
            float b0 = bin[cn], b1 = bin[cn + 1];
            float v0 = C[mt][nt][0] + b0, v1 = C[mt][nt][1] + b1;
            float v2 = C[mt][nt][2] + b0, v3 = C[mt][nt][3] + b1;
            if (is_gate) {
                v0 = 1.0f / (1.0f + __expf(-v0));
                v1 = 1.0f / (1.0f + __expf(-v1));
                v2 = 1.0f / (1.0f + __expf(-v2));
                v3 = 1.0f / (1.0f + __expf(-v3));
            }
            *(float2*)&dst[(size_t)r * D_SZ + cn - csub]       = make_float2(v0, v1);
            *(float2*)&dst[(size_t)(r + 8) * D_SZ + cn - csub] = make_float2(v2, v3);
        }
    }
}

// ---------------------------------------------------------------------------
// Phase 2: 4096-step recurrence. 4 groups x 32 CTAs (2 batches/group).
// CTA owns 32 cols of its 2 batches. Warp w (0..7) owns 4 cols, full K;
// lane owns a 32-d slice (weights 64 u64 in regs). In-warp butterfly
// reduction only — no cross-warp reduce, no partial matrix.
// ---------------------------------------------------------------------------
__global__ __launch_bounds__(256, 1) void phase2_scan(
    const float* __restrict__ Ws, const float* __restrict__ bs,
    float* __restrict__ out)
{
    __shared__ float4 st4[512];    // 8 KB: 2 batches x 1024 cols, swizzled

    const int tid   = threadIdx.x;
    const int lane  = tid & 31;
    const int w     = tid >> 5;           // 0..7: column group (4 cols)
    const int blk   = blockIdx.x;
    const int grp   = blk >> 5;           // 0..3: batches {2grp, 2grp+1}
    const int chunk = blk & 31;           // cols [32*chunk, +32)
    const int d0    = 32 * lane;

    // Weights: Wn[c][j] = pair (Ws[e][d0+2j], Ws[e][d0+2j+1]), e=32chunk+4w+c
    u64 Wn[4][16];
    #pragma unroll
    for (int c = 0; c < 4; ++c) {
        const ulonglong2* wp =
            (const ulonglong2*)&Ws[(size_t)(chunk * 32 + 4 * w + c) * D_SZ + d0];
        #pragma unroll
        for (int q = 0; q < 8; ++q) {
            ulonglong2 v = wp[q];
            Wn[c][2 * q] = v.x; Wn[c][2 * q + 1] = v.y;
        }
    }

    // epilogue (lanes 0..7): r = lane -> c = r&3, local batch bl = r>>2
    const int ec   = chunk * 32 + 4 * w + (lane & 3);
    const int ebl  = lane >> 2;               // 0..1
    const int eb   = 2 * grp + ebl;           // global batch
    const float bsv = (lane < 8) ? bs[ec] : 0.0f;
    const int sf   = ebl * D_SZ + ec;         // state float idx in st4
    const int sfp  = (((sf >> 2) ^ (((sf >> 2) >> 3) & 7)) << 2) | (sf & 3);

    volatile unsigned* cnt = (volatile unsigned*)&g_cnt[grp];

    for (int t = 0; t < S_LEN; ++t) {
        // prefetch gate/proj (independent of state)
        float gv = 0.0f, pv = 0.0f;
        if (lane < 8) {
            size_t gi = ((size_t)eb * S_LEN + t) * D_SZ + ec;
            gv = __ldcg(&g_gate[gi]);
            pv = __ldcg(&g_proj[gi]);
        }

        // wait for all 32 CTAs of this group to have produced state t
        if (tid == 0) {
            unsigned target = (unsigned)(32 * t);
            while (*cnt < target) __nanosleep(20);
            __threadfence();
        }
        __syncthreads();

        // stage this group's 2-batch state (8 KB), swizzled
        const float4* cur = (const float4*)&g_state[t & 1][grp * 2 * D_SZ];
        {
            int i0 = tid;
            int i1 = tid + 256;
            st4[i0 ^ ((i0 >> 3) & 7)] = __ldcg(&cur[i0]);
            st4[i1 ^ ((i1 >> 3) & 7)] = __ldcg(&cur[i1]);
        }
        __syncthreads();

        // partial dots over lane's 32-d slice: ac[b][c]
        u64 ac[2][4];
        #pragma unroll
        for (int b = 0; b < 2; ++b)
            #pragma unroll
            for (int c = 0; c < 4; ++c) ac[b][c] = 0ull;

        #pragma unroll
        for (int b = 0; b < 2; ++b) {
            #pragma unroll
            for (int q = 0; q < 8; ++q) {
                int a = b * 256 + 8 * lane + q;
                ulonglong2 sv = *(const ulonglong2*)&st4[a ^ ((a >> 3) & 7)];
                #pragma unroll
                for (int c = 0; c < 4; ++c) {
                    ac[b][c] = ffma2(Wn[c][2 * q],     sv.x, ac[b][c]);
                    ac[b][c] = ffma2(Wn[c][2 * q + 1], sv.y, ac[b][c]);
                }
            }
        }

        // in-warp butterfly: 8 independent sums, all lanes get results
        float s[8];
        #pragma unroll
        for (int b = 0; b < 2; ++b)
            #pragma unroll
            for (int c = 0; c < 4; ++c) {
                float2 f = u2f(ac[b][c]);
                s[b * 4 + c] = f.x + f.y;
            }
        #pragma unroll
        for (int m = 16; m > 0; m >>= 1)
            #pragma unroll
            for (int i = 0; i < 8; ++i)
                s[i] += __shfl_xor_sync(0xffffffffu, s[i], m);

        // gated epilogue: lanes 0..7 of every warp (64 outputs/CTA)
        if (lane < 8) {
            float mix  = s[lane] + bsv + pv;
            float sold = ((const float*)st4)[sfp];
            float nxt  = gv * mix + (1.0f - gv) * sold;
            out[((size_t)eb * S_LEN + t) * D_SZ + ec] = nxt;
            __stcg(&g_state[(t + 1) & 1][eb * D_SZ + ec], nxt);
        }
        __syncthreads();

        // arrive
        if (tid == 0) {
            __threadfence();
            atomicAdd(&g_cnt[grp], 1u);
        }
    }
}

// ---------------------------------------------------------------------------
extern "C" void kernel_launch(void* const* d_in, const int* in_sizes, int n_in,
                              void* d_out, int out_size) {
    const float* x    = (const float*)d_in[0];
    const float* W_in = (const float*)d_in[1];
    const float* b_in = (const float*)d_in[2];
    const float* W_s  = (const float*)d_in[3];
    const float* b_s  = (const float*)d_in[4];
    float* out = (float*)d_out;

    dim3 g1(16, 256);
    phase1_hmma<<<g1, 256>>>(x, W_in, b_in);
    phase2_scan<<<128, 256>>>(W_s, b_s, out);
}

// round 10
// speedup vs baseline: 1.0501x; 1.0501x over previous
#include <cuda_runtime.h>
#include <cuda_bf16.h>
#include <cstdint>
#include <cstddef>

#define S_LEN 4096
#define B_SZ  8
#define D_SZ  1024
#define M_TOT (B_SZ * S_LEN)

__device__ float g_gate[(size_t)M_TOT * D_SZ];
__device__ float g_proj[(size_t)M_TOT * D_SZ];
__device__ float g_state[2][B_SZ * D_SZ];
__device__ unsigned g_cnt[4];
// pre-converted bf16 hi/lo operands
__device__ unsigned short g_xh[(size_t)M_TOT * D_SZ];
__device__ unsigned short g_xl[(size_t)M_TOT * D_SZ];
__device__ unsigned short g_wh[(size_t)2 * D_SZ * D_SZ];
__device__ unsigned short g_wl[(size_t)2 * D_SZ * D_SZ];

typedef unsigned long long u64;

__device__ __forceinline__ u64 ffma2(u64 a, u64 b, u64 c) {
    u64 d;
    asm("fma.rn.f32x2 %0, %1, %2, %3;" : "=l"(d) : "l"(a), "l"(b), "l"(c));
    return d;
}
__device__ __forceinline__ float2 u2f(u64 v) {
    float2 f;
    asm("mov.b64 {%0, %1}, %2;" : "=f"(f.x), "=f"(f.y) : "l"(v));
    return f;
}
__device__ __forceinline__ void mma16816(float* c, const unsigned* a,
                                         unsigned b0, unsigned b1) {
    asm("mma.sync.aligned.m16n8k16.row.col.f32.bf16.bf16.f32 "
        "{%0,%1,%2,%3}, {%4,%5,%6,%7}, {%8,%9}, {%0,%1,%2,%3};"
        : "+f"(c[0]), "+f"(c[1]), "+f"(c[2]), "+f"(c[3])
        : "r"(a[0]), "r"(a[1]), "r"(a[2]), "r"(a[3]), "r"(b0), "r"(b1));
}
__device__ __forceinline__ void ldsm4(unsigned* r, unsigned addr) {
    asm volatile("ldmatrix.sync.aligned.m8n8.x4.shared.b16 {%0,%1,%2,%3}, [%4];"
                 : "=r"(r[0]), "=r"(r[1]), "=r"(r[2]), "=r"(r[3]) : "r"(addr));
}
__device__ __forceinline__ void cpasync16(unsigned saddr, const void* gaddr) {
    asm volatile("cp.async.ca.shared.global [%0], [%1], 16;"
                 :: "r"(saddr), "l"(gaddr));
}
__device__ __forceinline__ unsigned smem_u32(const void* p) {
    unsigned r;
    asm("{ .reg .u64 t; cvta.to.shared.u64 t, %1; cvt.u32.u64 %0, t; }"
        : "=r"(r) : "l"(p));
    return r;
}
__device__ __forceinline__ void pack_hilo(float x, float y,
                                          unsigned& h, unsigned& l) {
    __nv_bfloat16 hx = __float2bfloat16_rn(x);
    __nv_bfloat16 hy = __float2bfloat16_rn(y);
    __nv_bfloat16 lx = __float2bfloat16_rn(x - __bfloat162float(hx));
    __nv_bfloat16 ly = __float2bfloat16_rn(y - __bfloat162float(hy));
    h = (unsigned)__bfloat16_as_ushort(hx) | ((unsigned)__bfloat16_as_ushort(hy) << 16);
    l = (unsigned)__bfloat16_as_ushort(lx) | ((unsigned)__bfloat16_as_ushort(ly) << 16);
}

// ---------------------------------------------------------------------------
// Init: zero counters/state; convert x and W_in to bf16 hi/lo arrays.
// ---------------------------------------------------------------------------
#define NX4 ((size_t)M_TOT * D_SZ / 4)
#define NW4 ((size_t)2 * D_SZ * D_SZ / 4)
__global__ void init_convert(const float* __restrict__ X,
                             const float* __restrict__ Win) {
    size_t tid = (size_t)blockIdx.x * blockDim.x + threadIdx.x;
    size_t stride = (size_t)gridDim.x * blockDim.x;
    if (blockIdx.x == 0) {
        if (threadIdx.x < 4) g_cnt[threadIdx.x] = 0u;
        for (int i = threadIdx.x; i < B_SZ * D_SZ; i += blockDim.x)
            g_state[0][i] = 0.0f;
    }
    for (size_t i = tid; i < NX4; i += stride) {
        float4 v = ((const float4*)X)[i];
        uint2 h, l;
        pack_hilo(v.x, v.y, h.x, l.x);
        pack_hilo(v.z, v.w, h.y, l.y);
        ((uint2*)g_xh)[i] = h;
        ((uint2*)g_xl)[i] = l;
    }
    for (size_t i = tid; i < NW4; i += stride) {
        float4 v = ((const float4*)Win)[i];
        uint2 h, l;
        pack_hilo(v.x, v.y, h.x, l.x);
        pack_hilo(v.z, v.w, h.y, l.y);
        ((uint2*)g_wh)[i] = h;
        ((uint2*)g_wl)[i] = l;
    }
}

// ---------------------------------------------------------------------------
// Phase 1: z = X@Win^T + bin via mma.sync bf16 hi/lo (3 terms), with
// pre-converted operands, ldmatrix fragments, cp.async double buffering.
// CTA 128x128, K blocks of 32. 8 warps: (w&3)*32 rows x (w>>2)*64 cols.
// smem: 2 stages x 4 bufs (Ah, Al, Bh, Bl), each 128 rows x 80B (20 u32).
// 80B row stride: 16B-aligned rows; ldmatrix bank-start 20r mod 32 =
// {0,20,8,28,16,4,24,12} -> disjoint 4-bank ranges, conflict-free.
// ---------------------------------------------------------------------------
#define SROW 20
#define BUFU (128 * SROW)        // 2560 u32 per buffer
#define STGU (4 * BUFU)          // 10240 u32 per stage
#define P1_SMEM (2 * STGU * 4)   // 81920 bytes

__device__ __forceinline__ void stage_k(unsigned sm_base, unsigned stg,
                                        int m0, int n0, int k0, int tid) {
    const int buf = tid >> 6;
    const int t64 = tid & 63;
    const unsigned short* src = (buf == 0) ? g_xh : (buf == 1) ? g_xl
                              : (buf == 2) ? g_wh : g_wl;
    const int rb = (buf < 2) ? m0 : n0;
    #pragma unroll
    for (int j = 0; j < 8; ++j) {
        int cidx = t64 + 64 * j;
        int row = cidx >> 2;
        int c = cidx & 3;
        const void* g = src + (size_t)(rb + row) * D_SZ + k0 + 8 * c;
        unsigned s = sm_base + 4u * (stg + buf * BUFU + row * SROW + c * 4);
        cpasync16(s, g);
    }
}

__global__ __launch_bounds__(256, 2) void phase1_hmma(
    const float* __restrict__ bin)
{
    extern __shared__ unsigned sm[];
    const unsigned sm_base = smem_u32(sm);
    const int tid = threadIdx.x;
    const int m0 = blockIdx.y * 128, n0 = blockIdx.x * 128;
    const int lane = tid & 31, w = tid >> 5;
    const int m_off = (w & 3) * 32;
    const int n_off = (w >> 2) * 64;

    // ldmatrix per-lane address components
    const int ti = lane >> 3, lr = lane & 7;
    const int a_r = (ti & 1) * 8 + lr;    // A: row-within-16, k-half ti>>1
    const int a_k = (ti >> 1) * 4;
    const int b_r = (ti >> 1) * 8 + lr;   // B: n-half ti>>1, k-half ti&1
    const int b_k = (ti & 1) * 4;

    float C[2][8][4];
    #pragma unroll
    for (int mt = 0; mt < 2; ++mt)
        #pragma unroll
        for (int nt = 0; nt < 8; ++nt)
            #pragma unroll
            for (int q = 0; q < 4; ++q) C[mt][nt][q] = 0.0f;

    stage_k(sm_base, 0, m0, n0, 0, tid);
    asm volatile("cp.async.commit_group;" ::: "memory");

    for (int it = 0; it < 32; ++it) {
        if (it < 31) {
            stage_k(sm_base, ((it + 1) & 1) * STGU, m0, n0, 32 * (it + 1), tid);
            asm volatile("cp.async.commit_group;" ::: "memory");
            asm volatile("cp.async.wait_group 1;" ::: "memory");
        } else {
            asm volatile("cp.async.wait_group 0;" ::: "memory");
        }
        __syncthreads();

        const unsigned stg = (it & 1) * STGU;
        #pragma unroll
        for (int ks = 0; ks < 2; ++ks) {
            const int ku = ks * 8;
            unsigned ah[2][4], al[2][4];
            #pragma unroll
            for (int mt = 0; mt < 2; ++mt) {
                int row = m_off + mt * 16 + a_r;
                unsigned addr = sm_base + 4u * (stg + row * SROW + ku + a_k);
                ldsm4(ah[mt], addr);
                ldsm4(al[mt], addr + 4u * BUFU);
            }
            #pragma unroll
            for (int p = 0; p < 4; ++p) {
                int row = n_off + p * 16 + b_r;
                unsigned addr = sm_base + 4u * (stg + 2 * BUFU + row * SROW + ku + b_k);
                unsigned bh[4], bl[4];
                ldsm4(bh, addr);
                ldsm4(bl, addr + 4u * BUFU);
                #pragma unroll
                for (int mt = 0; mt < 2; ++mt) {
                    mma16816(C[mt][2 * p],     ah[mt], bh[0], bh[1]);
                    mma16816(C[mt][2 * p],     ah[mt], bl[0], bl[1]);
                    mma16816(C[mt][2 * p],     al[mt], bh[0], bh[1]);
                    mma16816(C[mt][2 * p + 1], ah[mt], bh[2], bh[3]);
                    mma16816(C[mt][2 * p + 1], ah[mt], bl[2], bl[3]);
                    mma16816(C[mt][2 * p + 1], al[mt], bh[2], bh[3]);
                }
            }
        }
        __syncthreads();
    }

    // epilogue: bias + sigmoid split (validated R7 layout)
    const int fr = lane >> 2, fc = lane & 3;
    const bool is_gate = (n0 < D_SZ);
    float* dst = is_gate ? g_gate : g_proj;
    const int csub = is_gate ? 0 : D_SZ;
    #pragma unroll
    for (int mt = 0; mt < 2; ++mt) {
        const int r = m0 + m_off + mt * 16 + fr;
        #pragma unroll
        for (int nt = 0; nt < 8; ++nt) {
            const int cn = n0 + n_off + nt * 8 + fc * 2;
            float b0 = bin[cn], b1 = bin[cn + 1];
            float v0 = C[mt][nt][0] + b0, v1 = C[mt][nt][1] + b1;
            float v2 = C[mt][nt][2] + b0, v3 = C[mt][nt][3] + b1;
            if (is_gate) {
                v0 = 1.0f / (1.0f + __expf(-v0));
                v1 = 1.0f / (1.0f + __expf(-v1));
                v2 = 1.0f / (1.0f + __expf(-v2));
                v3 = 1.0f / (1.0f + __expf(-v3));
            }
            *(float2*)&dst[(size_t)r * D_SZ + cn - csub]       = make_float2(v0, v1);
            *(float2*)&dst[(size_t)(r + 8) * D_SZ + cn - csub] = make_float2(v2, v3);
        }
    }
}

// ---------------------------------------------------------------------------
// Phase 2: verbatim R8 (proven). 4 groups x 32 CTAs, in-warp butterfly.
// ---------------------------------------------------------------------------
__global__ __launch_bounds__(256, 1) void phase2_scan(
    const float* __restrict__ Ws, const float* __restrict__ bs,
    float* __restrict__ out)
{
    __shared__ float4 st4[512];

    const int tid   = threadIdx.x;
    const int lane  = tid & 31;
    const int w     = tid >> 5;
    const int blk   = blockIdx.x;
    const int grp   = blk >> 5;
    const int chunk = blk & 31;
    const int d0    = 32 * lane;

    u64 Wn[4][16];
    #pragma unroll
    for (int c = 0; c < 4; ++c) {
        const ulonglong2* wp =
            (const ulonglong2*)&Ws[(size_t)(chunk * 32 + 4 * w + c) * D_SZ + d0];
        #pragma unroll
        for (int q = 0; q < 8; ++q) {
            ulonglong2 v = wp[q];
            Wn[c][2 * q] = v.x; Wn[c][2 * q + 1] = v.y;
        }
    }

    const int ec   = chunk * 32 + 4 * w + (lane & 3);
    const int ebl  = lane >> 2;
    const int eb   = 2 * grp + (ebl & 1);
    const float bsv = (lane < 8) ? bs[ec] : 0.0f;
    const int sf   = (ebl & 1) * D_SZ + ec;
    const int sfp  = (((sf >> 2) ^ (((sf >> 2) >> 3) & 7)) << 2) | (sf & 3);

    volatile unsigned* cnt = (volatile unsigned*)&g_cnt[grp];

    for (int t = 0; t < S_LEN; ++t) {
        float gv = 0.0f, pv = 0.0f;
        if (lane < 8) {
            size_t gi = ((size_t)eb * S_LEN + t) * D_SZ + ec;
            gv = __ldcg(&g_gate[gi]);
            pv = __ldcg(&g_proj[gi]);
        }

        if (tid == 0) {
            unsigned target = (unsigned)(32 * t);
            while (*cnt < target) __nanosleep(20);
            __threadfence();
        }
        __syncthreads();

        const float4* cur = (const float4*)&g_state[t & 1][grp * 2 * D_SZ];
        {
            int i0 = tid;
            int i1 = tid + 256;
            st4[i0 ^ ((i0 >> 3) & 7)] = __ldcg(&cur[i0]);
            st4[i1 ^ ((i1 >> 3) & 7)] = __ldcg(&cur[i1]);
        }
        __syncthreads();

        u64 ac[2][4];
        #pragma unroll
        for (int b = 0; b < 2; ++b)
            #pragma unroll
            for (int c = 0; c < 4; ++c) ac[b][c] = 0ull;

        #pragma unroll
        for (int b = 0; b < 2; ++b) {
            #pragma unroll
            for (int q = 0; q < 8; ++q) {
                int a = b * 256 + 8 * lane + q;
                ulonglong2 sv = *(const ulonglong2*)&st4[a ^ ((a >> 3) & 7)];
                #pragma unroll
                for (int c = 0; c < 4; ++c) {
                    ac[b][c] = ffma2(Wn[c][2 * q],     sv.x, ac[b][c]);
                    ac[b][c] = ffma2(Wn[c][2 * q + 1], sv.y, ac[b][c]);
                }
            }
        }

        float s[8];
        #pragma unroll
        for (int b = 0; b < 2; ++b)
            #pragma unroll
            for (int c = 0; c < 4; ++c) {
                float2 f = u2f(ac[b][c]);
                s[b * 4 + c] = f.x + f.y;
            }
        #pragma unroll
        for (int m = 16; m > 0; m >>= 1)
            #pragma unroll
            for (int i = 0; i < 8; ++i)
                s[i] += __shfl_xor_sync(0xffffffffu, s[i], m);

        if (lane < 8) {
            float mix  = s[lane] + bsv + pv;
            float sold = ((const float*)st4)[sfp];
            float nxt  = gv * mix + (1.0f - gv) * sold;
            out[((size_t)eb * S_LEN + t) * D_SZ + ec] = nxt;
            __stcg(&g_state[(t + 1) & 1][eb * D_SZ + ec], nxt);
        }
        __syncthreads();

        if (tid == 0) {
            __threadfence();
            atomicAdd(&g_cnt[grp], 1u);
        }
    }
}

// ---------------------------------------------------------------------------
extern "C" void kernel_launch(void* const* d_in, const int* in_sizes, int n_in,
                              void* d_out, int out_size) {
    const float* x    = (const float*)d_in[0];
    const float* W_in = (const float*)d_in[1];
    const float* b_in = (const float*)d_in[2];
    const float* W_s  = (const float*)d_in[3];
    const float* b_s  = (const float*)d_in[4];
    float* out = (float*)d_out;

    cudaFuncSetAttribute(phase1_hmma,
                         cudaFuncAttributeMaxDynamicSharedMemorySize, P1_SMEM);

    init_convert<<<4096, 256>>>(x, W_in);
    dim3 g1(16, 256);
    phase1_hmma<<<g1, 256, P1_SMEM>>>(b_in);
    phase2_scan<<<128, 256>>>(W_s, b_s, out);
}

// round 11
// speedup vs baseline: 1.2877x; 1.2262x over previous
#include <cuda_runtime.h>
#include <cuda_bf16.h>
#include <cstdint>
#include <cstddef>

#define S_LEN 4096
#define B_SZ  8
#define D_SZ  1024
#define M_TOT (B_SZ * S_LEN)

__device__ float g_gate[(size_t)M_TOT * D_SZ];
__device__ float g_proj[(size_t)M_TOT * D_SZ];
__device__ float g_state[2][B_SZ * D_SZ];
__device__ unsigned g_cnt[4];
__device__ unsigned short g_xh[(size_t)M_TOT * D_SZ];
__device__ unsigned short g_xl[(size_t)M_TOT * D_SZ];
__device__ unsigned short g_wh[(size_t)2 * D_SZ * D_SZ];
__device__ unsigned short g_wl[(size_t)2 * D_SZ * D_SZ];

typedef unsigned long long u64;

__device__ __forceinline__ u64 ffma2(u64 a, u64 b, u64 c) {
    u64 d;
    asm("fma.rn.f32x2 %0, %1, %2, %3;" : "=l"(d) : "l"(a), "l"(b), "l"(c));
    return d;
}
__device__ __forceinline__ float2 u2f(u64 v) {
    float2 f;
    asm("mov.b64 {%0, %1}, %2;" : "=f"(f.x), "=f"(f.y) : "l"(v));
    return f;
}
__device__ __forceinline__ void mma16816(float* c, const unsigned* a,
                                         unsigned b0, unsigned b1) {
    asm("mma.sync.aligned.m16n8k16.row.col.f32.bf16.bf16.f32 "
        "{%0,%1,%2,%3}, {%4,%5,%6,%7}, {%8,%9}, {%0,%1,%2,%3};"
        : "+f"(c[0]), "+f"(c[1]), "+f"(c[2]), "+f"(c[3])
        : "r"(a[0]), "r"(a[1]), "r"(a[2]), "r"(a[3]), "r"(b0), "r"(b1));
}
__device__ __forceinline__ void ldsm4(unsigned* r, unsigned addr) {
    asm volatile("ldmatrix.sync.aligned.m8n8.x4.shared.b16 {%0,%1,%2,%3}, [%4];"
                 : "=r"(r[0]), "=r"(r[1]), "=r"(r[2]), "=r"(r[3]) : "r"(addr));
}
__device__ __forceinline__ void cpasync16(unsigned saddr, const void* gaddr) {
    asm volatile("cp.async.ca.shared.global [%0], [%1], 16;"
                 :: "r"(saddr), "l"(gaddr));
}
__device__ __forceinline__ unsigned smem_u32(const void* p) {
    unsigned r;
    asm("{ .reg .u64 t; cvta.to.shared.u64 t, %1; cvt.u32.u64 %0, t; }"
        : "=r"(r) : "l"(p));
    return r;
}
__device__ __forceinline__ unsigned ld_acq(const unsigned* p) {
    unsigned v;
    asm volatile("ld.acquire.gpu.global.u32 %0, [%1];" : "=r"(v) : "l"(p) : "memory");
    return v;
}
__device__ __forceinline__ void red_release_add(unsigned* p, unsigned v) {
    asm volatile("red.release.gpu.global.add.u32 [%0], %1;" :: "l"(p), "r"(v) : "memory");
}
__device__ __forceinline__ void pack_hilo(float x, float y,
                                          unsigned& h, unsigned& l) {
    __nv_bfloat16 hx = __float2bfloat16_rn(x);
    __nv_bfloat16 hy = __float2bfloat16_rn(y);
    __nv_bfloat16 lx = __float2bfloat16_rn(x - __bfloat162float(hx));
    __nv_bfloat16 ly = __float2bfloat16_rn(y - __bfloat162float(hy));
    h = (unsigned)__bfloat16_as_ushort(hx) | ((unsigned)__bfloat16_as_ushort(hy) << 16);
    l = (unsigned)__bfloat16_as_ushort(lx) | ((unsigned)__bfloat16_as_ushort(ly) << 16);
}

// ---------------------------------------------------------------------------
// Init: zero counters/state; convert x and W_in to bf16 hi/lo arrays.
// ---------------------------------------------------------------------------
#define NX4 ((size_t)M_TOT * D_SZ / 4)
#define NW4 ((size_t)2 * D_SZ * D_SZ / 4)
__global__ void init_convert(const float* __restrict__ X,
                             const float* __restrict__ Win) {
    size_t tid = (size_t)blockIdx.x * blockDim.x + threadIdx.x;
    size_t stride = (size_t)gridDim.x * blockDim.x;
    if (blockIdx.x == 0) {
        if (threadIdx.x < 4) g_cnt[threadIdx.x] = 0u;
        for (int i = threadIdx.x; i < B_SZ * D_SZ; i += blockDim.x)
            g_state[0][i] = 0.0f;
    }
    for (size_t i = tid; i < NX4; i += stride) {
        float4 v = ((const float4*)X)[i];
        uint2 h, l;
        pack_hilo(v.x, v.y, h.x, l.x);
        pack_hilo(v.z, v.w, h.y, l.y);
        ((uint2*)g_xh)[i] = h;
        ((uint2*)g_xl)[i] = l;
    }
    for (size_t i = tid; i < NW4; i += stride) {
        float4 v = ((const float4*)Win)[i];
        uint2 h, l;
        pack_hilo(v.x, v.y, h.x, l.x);
        pack_hilo(v.z, v.w, h.y, l.y);
        ((uint2*)g_wh)[i] = h;
        ((uint2*)g_wl)[i] = l;
    }
}

// ---------------------------------------------------------------------------
// Phase 1: HMMA bf16 hi/lo, pre-converted operands, ldmatrix, cp.async
// double buffering. (validated R10)
// ---------------------------------------------------------------------------
#define SROW 20
#define BUFU (128 * SROW)
#define STGU (4 * BUFU)
#define P1_SMEM (2 * STGU * 4)

__device__ __forceinline__ void stage_k(unsigned sm_base, unsigned stg,
                                        int m0, int n0, int k0, int tid) {
    const int buf = tid >> 6;
    const int t64 = tid & 63;
    const unsigned short* src = (buf == 0) ? g_xh : (buf == 1) ? g_xl
                              : (buf == 2) ? g_wh : g_wl;
    const int rb = (buf < 2) ? m0 : n0;
    #pragma unroll
    for (int j = 0; j < 8; ++j) {
        int cidx = t64 + 64 * j;
        int row = cidx >> 2;
        int c = cidx & 3;
        const void* g = src + (size_t)(rb + row) * D_SZ + k0 + 8 * c;
        unsigned s = sm_base + 4u * (stg + buf * BUFU + row * SROW + c * 4);
        cpasync16(s, g);
    }
}

__global__ __launch_bounds__(256, 2) void phase1_hmma(
    const float* __restrict__ bin)
{
    extern __shared__ unsigned sm[];
    const unsigned sm_base = smem_u32(sm);
    const int tid = threadIdx.x;
    const int m0 = blockIdx.y * 128, n0 = blockIdx.x * 128;
    const int lane = tid & 31, w = tid >> 5;
    const int m_off = (w & 3) * 32;
    const int n_off = (w >> 2) * 64;

    const int ti = lane >> 3, lr = lane & 7;
    const int a_r = (ti & 1) * 8 + lr;
    const int a_k = (ti >> 1) * 4;
    const int b_r = (ti >> 1) * 8 + lr;
    const int b_k = (ti & 1) * 4;

    float C[2][8][4];
    #pragma unroll
    for (int mt = 0; mt < 2; ++mt)
        #pragma unroll
        for (int nt = 0; nt < 8; ++nt)
            #pragma unroll
            for (int q = 0; q < 4; ++q) C[mt][nt][q] = 0.0f;

    stage_k(sm_base, 0, m0, n0, 0, tid);
    asm volatile("cp.async.commit_group;" ::: "memory");

    for (int it = 0; it < 32; ++it) {
        if (it < 31) {
            stage_k(sm_base, ((it + 1) & 1) * STGU, m0, n0, 32 * (it + 1), tid);
            asm volatile("cp.async.commit_group;" ::: "memory");
            asm volatile("cp.async.wait_group 1;" ::: "memory");
        } else {
            asm volatile("cp.async.wait_group 0;" ::: "memory");
        }
        __syncthreads();

        const unsigned stg = (it & 1) * STGU;
        #pragma unroll
        for (int ks = 0; ks < 2; ++ks) {
            const int ku = ks * 8;
            unsigned ah[2][4], al[2][4];
            #pragma unroll
            for (int mt = 0; mt < 2; ++mt) {
                int row = m_off + mt * 16 + a_r;
                unsigned addr = sm_base + 4u * (stg + row * SROW + ku + a_k);
                ldsm4(ah[mt], addr);
                ldsm4(al[mt], addr + 4u * BUFU);
            }
            #pragma unroll
            for (int p = 0; p < 4; ++p) {
                int row = n_off + p * 16 + b_r;
                unsigned addr = sm_base + 4u * (stg + 2 * BUFU + row * SROW + ku + b_k);
                unsigned bh[4], bl[4];
                ldsm4(bh, addr);
                ldsm4(bl, addr + 4u * BUFU);
                #pragma unroll
                for (int mt = 0; mt < 2; ++mt) {
                    mma16816(C[mt][2 * p],     ah[mt], bh[0], bh[1]);
                    mma16816(C[mt][2 * p],     ah[mt], bl[0], bl[1]);
                    mma16816(C[mt][2 * p],     al[mt], bh[0], bh[1]);
                    mma16816(C[mt][2 * p + 1], ah[mt], bh[2], bh[3]);
                    mma16816(C[mt][2 * p + 1], ah[mt], bl[2], bl[3]);
                    mma16816(C[mt][2 * p + 1], al[mt], bh[2], bh[3]);
                }
            }
        }
        __syncthreads();
    }

    const int fr = lane >> 2, fc = lane & 3;
    const bool is_gate = (n0 < D_SZ);
    float* dst = is_gate ? g_gate : g_proj;
    const int csub = is_gate ? 0 : D_SZ;
    #pragma unroll
    for (int mt = 0; mt < 2; ++mt) {
        const int r = m0 + m_off + mt * 16 + fr;
        #pragma unroll
        for (int nt = 0; nt < 8; ++nt) {
            const int cn = n0 + n_off + nt * 8 + fc * 2;
            float b0 = bin[cn], b1 = bin[cn + 1];
            float v0 = C[mt][nt][0] + b0, v1 = C[mt][nt][1] + b1;
            float v2 = C[mt][nt][2] + b0, v3 = C[mt][nt][3] + b1;
            if (is_gate) {
                v0 = 1.0f / (1.0f + __expf(-v0));
                v1 = 1.0f / (1.0f + __expf(-v1));
                v2 = 1.0f / (1.0f + __expf(-v2));
                v3 = 1.0f / (1.0f + __expf(-v3));
            }
            *(float2*)&dst[(size_t)r * D_SZ + cn - csub]       = make_float2(v0, v1);
            *(float2*)&dst[(size_t)(r + 8) * D_SZ + cn - csub] = make_float2(v2, v3);
        }
    }
}

// ---------------------------------------------------------------------------
// Phase 2: R8 structure + leaner sync chain:
//  - tight ld.acquire poll (no nanosleep)
//  - red.release arrival (no MEMBAR drain, no atomic return)
//  - no post-detect threadfence (acquire load orders state reads)
// ---------------------------------------------------------------------------
__global__ __launch_bounds__(256, 1) void phase2_scan(
    const float* __restrict__ Ws, const float* __restrict__ bs,
    float* __restrict__ out)
{
    __shared__ float4 st4[512];

    const int tid   = threadIdx.x;
    const int lane  = tid & 31;
    const int w     = tid >> 5;
    const int blk   = blockIdx.x;
    const int grp   = blk >> 5;
    const int chunk = blk & 31;
    const int d0    = 32 * lane;

    u64 Wn[4][16];
    #pragma unroll
    for (int c = 0; c < 4; ++c) {
        const ulonglong2* wp =
            (const ulonglong2*)&Ws[(size_t)(chunk * 32 + 4 * w + c) * D_SZ + d0];
        #pragma unroll
        for (int q = 0; q < 8; ++q) {
            ulonglong2 v = wp[q];
            Wn[c][2 * q] = v.x; Wn[c][2 * q + 1] = v.y;
        }
    }

    const int ec   = chunk * 32 + 4 * w + (lane & 3);
    const int ebl  = (lane >> 2) & 1;
    const int eb   = 2 * grp + ebl;
    const float bsv = (lane < 8) ? bs[ec] : 0.0f;
    const int sf   = ebl * D_SZ + ec;
    const int sfp  = (((sf >> 2) ^ (((sf >> 2) >> 3) & 7)) << 2) | (sf & 3);

    unsigned* cnt = &g_cnt[grp];

    for (int t = 0; t < S_LEN; ++t) {
        float gv = 0.0f, pv = 0.0f;
        if (lane < 8) {
            size_t gi = ((size_t)eb * S_LEN + t) * D_SZ + ec;
            gv = __ldcg(&g_gate[gi]);
            pv = __ldcg(&g_proj[gi]);
        }

        // tight acquire-poll on this group's counter
        if (tid == 0) {
            const unsigned target = (unsigned)(32 * t);
            while (ld_acq(cnt) < target) { }
        }
        __syncthreads();

        const float4* cur = (const float4*)&g_state[t & 1][grp * 2 * D_SZ];
        {
            int i0 = tid;
            int i1 = tid + 256;
            st4[i0 ^ ((i0 >> 3) & 7)] = __ldcg(&cur[i0]);
            st4[i1 ^ ((i1 >> 3) & 7)] = __ldcg(&cur[i1]);
        }
        __syncthreads();

        u64 ac[2][4];
        #pragma unroll
        for (int b = 0; b < 2; ++b)
            #pragma unroll
            for (int c = 0; c < 4; ++c) ac[b][c] = 0ull;

        #pragma unroll
        for (int b = 0; b < 2; ++b) {
            #pragma unroll
            for (int q = 0; q < 8; ++q) {
                int a = b * 256 + 8 * lane + q;
                ulonglong2 sv = *(const ulonglong2*)&st4[a ^ ((a >> 3) & 7)];
                #pragma unroll
                for (int c = 0; c < 4; ++c) {
                    ac[b][c] = ffma2(Wn[c][2 * q],     sv.x, ac[b][c]);
                    ac[b][c] = ffma2(Wn[c][2 * q + 1], sv.y, ac[b][c]);
                }
            }
        }

        float s[8];
        #pragma unroll
        for (int b = 0; b < 2; ++b)
            #pragma unroll
            for (int c = 0; c < 4; ++c) {
                float2 f = u2f(ac[b][c]);
                s[b * 4 + c] = f.x + f.y;
            }
        #pragma unroll
        for (int m = 16; m > 0; m >>= 1)
            #pragma unroll
            for (int i = 0; i < 8; ++i)
                s[i] += __shfl_xor_sync(0xffffffffu, s[i], m);

        if (lane < 8) {
            float mix  = s[lane] + bsv + pv;
            float sold = ((const float*)st4)[sfp];
            float nxt  = gv * mix + (1.0f - gv) * sold;
            out[((size_t)eb * S_LEN + t) * D_SZ + ec] = nxt;
            __stcg(&g_state[(t + 1) & 1][eb * D_SZ + ec], nxt);
        }
        __syncthreads();

        // arrival: release-ordered reduction (no separate fence)
        if (tid == 0) red_release_add(cnt, 1u);
    }
}

// ---------------------------------------------------------------------------
extern "C" void kernel_launch(void* const* d_in, const int* in_sizes, int n_in,
                              void* d_out, int out_size) {
    const float* x    = (const float*)d_in[0];
    const float* W_in = (const float*)d_in[1];
    const float* b_in = (const float*)d_in[2];
    const float* W_s  = (const float*)d_in[3];
    const float* b_s  = (const float*)d_in[4];
    float* out = (float*)d_out;

    cudaFuncSetAttribute(phase1_hmma,
                         cudaFuncAttributeMaxDynamicSharedMemorySize, P1_SMEM);

    init_convert<<<4096, 256>>>(x, W_in);
    dim3 g1(16, 256);
    phase1_hmma<<<g1, 256, P1_SMEM>>>(b_in);
    phase2_scan<<<128, 256>>>(W_s, b_s, out);
}